// round 14
// baseline (speedup 1.0000x reference)
#include <cuda_runtime.h>
#include <cuda_fp16.h>
#include <cstdint>

// Shapes (fixed by the problem)
#define Bq 2
#define Nq 2048
#define Mq 32
#define Hq 8
#define Dq 64
#define Eq 512
#define Fq 512
#define Pq 6

// ---------------------------------------------------------------------------
// Scratch (graph-capture rules forbid cudaMalloc)
// ---------------------------------------------------------------------------
__device__ __half g_P[2][Bq * Nq * Eq];   // fp16 projections: [0]=Q, [1]=K
__device__ __half g_x16[2][Bq * Nq * Fq]; // fp16 inputs: [0]=qf, [1]=kf
__device__ __half g_w16[2][Eq * Fq];      // fp16 transposed weights [n][k]

// ---------------------------------------------------------------------------
// helpers
// ---------------------------------------------------------------------------
__device__ __forceinline__ uint32_t smem_u32(const void* p) {
    uint32_t a;
    asm("{ .reg .u64 t; cvta.to.shared.u64 t, %1; cvt.u32.u64 %0, t; }" : "=r"(a) : "l"(p));
    return a;
}
__device__ __forceinline__ void cpasync16(uint32_t s, const void* g) {
    asm volatile("cp.async.cg.shared.global [%0], [%1], 16;" :: "r"(s), "l"(g));
}
__device__ __forceinline__ void ldsm_x4(uint32_t& r0, uint32_t& r1, uint32_t& r2, uint32_t& r3,
                                        uint32_t addr) {
    asm volatile("ldmatrix.sync.aligned.m8n8.x4.shared.b16 {%0,%1,%2,%3}, [%4];"
                 : "=r"(r0), "=r"(r1), "=r"(r2), "=r"(r3) : "r"(addr));
}
__device__ __forceinline__ void ldsm_x2(uint32_t& r0, uint32_t& r1, uint32_t addr) {
    asm volatile("ldmatrix.sync.aligned.m8n8.x2.shared.b16 {%0,%1}, [%2];"
                 : "=r"(r0), "=r"(r1) : "r"(addr));
}
__device__ __forceinline__ void mma_f16(float* c, const uint32_t* a, uint32_t b0, uint32_t b1) {
    asm volatile(
        "mma.sync.aligned.m16n8k16.row.col.f32.f16.f16.f32 "
        "{%0,%1,%2,%3}, {%4,%5,%6,%7}, {%8,%9}, {%0,%1,%2,%3};"
        : "+f"(c[0]), "+f"(c[1]), "+f"(c[2]), "+f"(c[3])
        : "r"(a[0]), "r"(a[1]), "r"(a[2]), "r"(a[3]), "r"(b0), "r"(b1));
}
__device__ __forceinline__ void h8_to_f(const uint4& kv, float* f) {
    const __half2* hp = reinterpret_cast<const __half2*>(&kv);
#pragma unroll
    for (int i = 0; i < 4; i++) {
        float2 t = __half22float2(hp[i]);
        f[2 * i] = t.x;
        f[2 * i + 1] = t.y;
    }
}
__device__ __forceinline__ float red16(float s) {
    s += __shfl_xor_sync(0xffffffffu, s, 1);
    s += __shfl_xor_sync(0xffffffffu, s, 2);
    s += __shfl_xor_sync(0xffffffffu, s, 4);
    s += __shfl_xor_sync(0xffffffffu, s, 8);
    return s;
}
__device__ __forceinline__ float red8(float s) {
    s += __shfl_xor_sync(0xffffffffu, s, 1);
    s += __shfl_xor_sync(0xffffffffu, s, 2);
    s += __shfl_xor_sync(0xffffffffu, s, 4);
    return s;
}

// ---------------------------------------------------------------------------
// prep (R9 exact): blocks 0..1023 convert X fp32->fp16 (2 float4/thread);
// blocks 1024..1279 transpose+convert W. z=0 -> (qf,Wq); z=1 -> (kf,Wk).
// ---------------------------------------------------------------------------
__global__ __launch_bounds__(256) void prep_kernel(
    const float* __restrict__ qf, const float* __restrict__ kf,
    const float* __restrict__ Wq_, const float* __restrict__ Wk_)
{
    __shared__ float tile[32][33];
    const int z = blockIdx.z;
    const int tid = threadIdx.x;

    if (blockIdx.x < 1024) {
        const float* in = z ? kf : qf;
        __half* o = g_x16[z];
        const int f0 = blockIdx.x * 512 + tid;
        float4 x0 = ((const float4*)in)[f0];
        float4 x1 = ((const float4*)in)[f0 + 256];
        __half2 a0 = __floats2half2_rn(x0.x, x0.y);
        __half2 a1 = __floats2half2_rn(x0.z, x0.w);
        __half2 b0 = __floats2half2_rn(x1.x, x1.y);
        __half2 b1 = __floats2half2_rn(x1.z, x1.w);
        ((uint2*)o)[f0]       = make_uint2(*(uint32_t*)&a0, *(uint32_t*)&a1);
        ((uint2*)o)[f0 + 256] = make_uint2(*(uint32_t*)&b0, *(uint32_t*)&b1);
    } else {
        const int bx = blockIdx.x - 1024;               // 0..255
        const float* in = z ? Wk_ : Wq_;
        __half* o = g_w16[z];
        const int tx = tid & 31, ty = tid >> 5;         // 32 x 8
        const int n0 = (bx & 15) * 32, k0 = (bx >> 4) * 32;
#pragma unroll
        for (int j = 0; j < 4; j++)
            tile[ty + j * 8][tx] = in[(size_t)(k0 + ty + j * 8) * Eq + n0 + tx];
        __syncthreads();
#pragma unroll
        for (int j = 0; j < 4; j++)
            o[(size_t)(n0 + ty + j * 8) * Fq + k0 + tx] = __float2half_rn(tile[tx][ty + j * 8]);
    }
}

// ---------------------------------------------------------------------------
// GEMM (R9 exact): single-pass fp16 mma.sync, P[z] = X16 @ W16, fp16 out.
// ---------------------------------------------------------------------------
#define KC 32
#define LDE 40
#define TILE_B (128 * LDE * 2)
#define BUF_B (2 * TILE_B)
#define GEMM_SMEM (2 * BUF_B)        // 40960

__global__ __launch_bounds__(256, 2) void gemm_tc_kernel()
{
    extern __shared__ char smem[];
    const uint32_t sbase = smem_u32(smem);
    const int tid = threadIdx.x;
    const int wid = tid >> 5;
    const int lane = tid & 31;
    const int z = blockIdx.z;
    const int rowBase = blockIdx.y * 128;
    const int colBase = blockIdx.x * 128;

    const __half* X = g_x16[z];
    const __half* W = g_w16[z];
    __half* C = g_P[z];

    const int wm = (wid >> 2) * 64;
    const int wn = (wid & 3) * 32;

    const int r0a = tid >> 2, s0 = (tid & 3) * 8;
    const int r1a = (tid + 256) >> 2;

    float acc[4][4][4];
#pragma unroll
    for (int mt = 0; mt < 4; mt++)
#pragma unroll
        for (int nt = 0; nt < 4; nt++)
#pragma unroll
            for (int i = 0; i < 4; i++) acc[mt][nt][i] = 0.f;

    auto stage = [&](int buf, int kt) {
        const uint32_t sb = sbase + buf * BUF_B;
#pragma unroll
        for (int t = 0; t < 2; t++) {
            const int row = t ? r1a : r0a;
            const uint32_t so = (uint32_t)(row * LDE + s0) * 2;
            cpasync16(sb + so,          X + (size_t)(rowBase + row) * Fq + kt + s0);
            cpasync16(sb + TILE_B + so, W + (size_t)(colBase + row) * Fq + kt + s0);
        }
        asm volatile("cp.async.commit_group;");
    };

    const int lj = lane >> 3, lr = lane & 7;
    const int arow = (lj & 1) * 8 + lr;
    const int acol = (lj >> 1) * 8;
    const int brow = (lj >> 1) * 8 + lr;
    const int bcol = (lj & 1) * 8;

    stage(0, 0);

    const int NCHUNK = Fq / KC;               // 16
    for (int c = 0; c < NCHUNK; c++) {
        if (c + 1 < NCHUNK) stage((c + 1) & 1, (c + 1) * KC);
        if (c + 1 < NCHUNK) asm volatile("cp.async.wait_group 1;");
        else                asm volatile("cp.async.wait_group 0;");
        __syncthreads();

        const uint32_t sb = sbase + (c & 1) * BUF_B;
#pragma unroll
        for (int ks = 0; ks < 2; ks++) {
            const int kof = ks * 16;
            uint32_t a[4][4], bfr[2][4];
#pragma unroll
            for (int mt = 0; mt < 4; mt++)
                ldsm_x4(a[mt][0], a[mt][1], a[mt][2], a[mt][3],
                        sb + (uint32_t)((wm + mt * 16 + arow) * LDE + kof + acol) * 2);
#pragma unroll
            for (int np = 0; np < 2; np++)
                ldsm_x4(bfr[np][0], bfr[np][1], bfr[np][2], bfr[np][3],
                        sb + TILE_B + (uint32_t)((wn + np * 16 + brow) * LDE + kof + bcol) * 2);
#pragma unroll
            for (int mt = 0; mt < 4; mt++)
#pragma unroll
                for (int nt = 0; nt < 4; nt++)
                    mma_f16(acc[mt][nt], a[mt],
                            bfr[nt >> 1][(nt & 1) * 2], bfr[nt >> 1][(nt & 1) * 2 + 1]);
        }
        __syncthreads();
    }

    const int g = lane >> 2, tg = lane & 3;
#pragma unroll
    for (int mt = 0; mt < 4; mt++)
#pragma unroll
        for (int nt = 0; nt < 4; nt++) {
            const int row = rowBase + wm + mt * 16 + g;
            const int col = colBase + wn + nt * 8 + 2 * tg;
            *(__half2*)(C + (size_t)row * Eq + col) =
                __floats2half2_rn(acc[mt][nt][0], acc[mt][nt][1]);
            *(__half2*)(C + (size_t)(row + 8) * Eq + col) =
                __floats2half2_rn(acc[mt][nt][2], acc[mt][nt][3]);
        }
}

// ---------------------------------------------------------------------------
// Fused epilogue v5: one CTA (256 thr, 8 warps) per token; content via mma.
//  phase1: cp.async gather 32 K rows -> ktile[32][520] (pad row = 1040B)
//          + replicate token's Q into qrep[8][520] (8 identical rows)
//  phase2: proj (warps 0-5, one Wl row each) / kb (warp 6) — overlaps gather
//  phase3: wait + sync
//  phase4: warp w: content[:, head w] = K_tile(32 x 64_w) @ Q_head_w via
//          2 m-tiles x 4 k16-steps of m16n8k16. B = qrep rows (all identical)
//          -> every output column equals content[m][w]; take column 0.
//  phase5: combine (m = tid>>3, h = tid&7)
// ---------------------------------------------------------------------------
#define KLD 520                       // halves per ktile/qrep row (1040 B)

struct FuseSmem {
    __half ktile[Mq][KLD];            // 33280 B
    __half qrep[Hq][KLD];             // 8320 B
    float proj[Pq][Hq];
    float kb[Hq];
    float cont[Mq][Hq];
};

__global__ __launch_bounds__(256) void fuse_kernel(
    const float* __restrict__ pl,     // (B,N,M,P)
    const int*   __restrict__ nbhd,   // (B,N,M)
    const float* __restrict__ Wl,     // (P,E)
    const float* __restrict__ u,      // 512 contiguous
    const float* __restrict__ v,      // 512 contiguous
    float*       __restrict__ out)    // (B,N,M,H)
{
    __shared__ FuseSmem sm;
    const uint32_t sb_kt = smem_u32(&sm.ktile[0][0]);
    const uint32_t sb_qr = smem_u32(&sm.qrep[0][0]);

    const int tok = blockIdx.x;       // 0..4095
    const int b = tok >> 11;
    const int tid = threadIdx.x;
    const int w = tid >> 5;
    const int l = tid & 31;

    const __half* Qh = g_P[0] + (size_t)tok * Eq;
    const __half* Khb = g_P[1] + (size_t)b * Nq * Eq;
    const int* nbp = nbhd + (size_t)tok * Mq;

    // ---- phase 1: async gather of 32 K rows (2048 x 16B segs, 8/thread) ----
#pragma unroll
    for (int i = 0; i < 8; i++) {
        const int seg = i * 256 + tid;
        const int row = seg >> 6;                 // 0..31
        const int so = (seg & 63) * 8;            // halves within row
        cpasync16(sb_kt + (uint32_t)(row * KLD + so) * 2,
                  Khb + (size_t)nbp[row] * Eq + so);
    }
    asm volatile("cp.async.commit_group;");

    // qrep: 8 identical rows of Q (thread: row = tid>>5, 16 halves at (tid&31)*16)
    {
        const int qr = tid >> 5;
        const int qc = (tid & 31) * 16;
        uint4 qa = *(const uint4*)(Qh + qc);
        uint4 qb = *(const uint4*)(Qh + qc + 8);
        *(uint4*)&sm.qrep[qr][qc]     = qa;
        *(uint4*)&sm.qrep[qr][qc + 8] = qb;
    }

    // ---- phase 2: proj (warps 0-5) / kb (warp 6); overlaps the gather ----
    if (w < 6) {
        const int hsub = l >> 4;
        const float* wlr = Wl + w * Eq;
        float psum[4];
#pragma unroll
        for (int c = 0; c < 4; c++) {
            uint2 qp = *(const uint2*)(Qh + c * 128 + l * 4);
            float2 q0 = __half22float2(*(const __half2*)&qp.x);
            float2 q1 = __half22float2(*(const __half2*)&qp.y);
            float4 wv = *(const float4*)(wlr + c * 128 + l * 4);
            float4 vf = *(const float4*)(v + c * 128 + l * 4);
            float s = 0.f;
            s = fmaf(wv.x, q0.x + vf.x, s);
            s = fmaf(wv.y, q0.y + vf.y, s);
            s = fmaf(wv.z, q1.x + vf.z, s);
            s = fmaf(wv.w, q1.y + vf.w, s);
            psum[c] = red16(s);
        }
        if ((l & 15) == 0) {
#pragma unroll
            for (int c = 0; c < 4; c++) sm.proj[w][2 * c + hsub] = psum[c];
        }
    } else if (w == 6) {
        const __half* Kg = g_P[1] + (size_t)tok * Eq;
#pragma unroll
        for (int c = 0; c < 2; c++) {
            uint4 kk = *(const uint4*)(Kg + c * 256 + l * 8);
            float kf[8];
            h8_to_f(kk, kf);
            float4 u0 = *(const float4*)(u + c * 256 + l * 8);
            float4 u1 = *(const float4*)(u + c * 256 + l * 8 + 4);
            float s = 0.f;
            s = fmaf(kf[0], u0.x, s); s = fmaf(kf[1], u0.y, s);
            s = fmaf(kf[2], u0.z, s); s = fmaf(kf[3], u0.w, s);
            s = fmaf(kf[4], u1.x, s); s = fmaf(kf[5], u1.y, s);
            s = fmaf(kf[6], u1.z, s); s = fmaf(kf[7], u1.w, s);
            s = red8(s);
            if ((l & 7) == 0) sm.kb[c * 4 + (l >> 3)] = s;
        }
    }

    // ---- phase 3: gather complete + qrep visible ----
    asm volatile("cp.async.wait_group 0;");
    __syncthreads();

    // ---- phase 4: content via mma. warp w covers head w (k in [64w,64w+64)) ----
    {
        const int lj = l >> 3, lr = l & 7;
        const int arow = (lj & 1) * 8 + lr;       // A frag: m within tile
        const int acol = (lj >> 1) * 8;           // A frag: k offset within 16
        const int brow = l & 7;                   // B frag: n row (lanes 0-15 used)
        const int bcol = ((l >> 3) & 1) * 8;      // B frag: k offset within 16

        float c0[4] = {0.f, 0.f, 0.f, 0.f};      // m-tile 0 (rows 0-15)
        float c1[4] = {0.f, 0.f, 0.f, 0.f};      // m-tile 1 (rows 16-31)
#pragma unroll
        for (int s4 = 0; s4 < 4; s4++) {
            const int ks = (w * 4 + s4) * 16;     // k base for this step
            uint32_t b0, b1;
            ldsm_x2(b0, b1, sb_qr + (uint32_t)(brow * KLD + ks + bcol) * 2);
            uint32_t a[4];
            ldsm_x4(a[0], a[1], a[2], a[3],
                    sb_kt + (uint32_t)((arow) * KLD + ks + acol) * 2);
            mma_f16(c0, a, b0, b1);
            ldsm_x4(a[0], a[1], a[2], a[3],
                    sb_kt + (uint32_t)((16 + arow) * KLD + ks + acol) * 2);
            mma_f16(c1, a, b0, b1);
        }
        // all 8 output columns equal content[m][w]; take column 0 (lanes l&3==0)
        if ((l & 3) == 0) {
            const int g = l >> 2;
            sm.cont[g][w]      = c0[0];
            sm.cont[g + 8][w]  = c0[2];
            sm.cont[g + 16][w] = c1[0];
            sm.cont[g + 24][w] = c1[2];
        }
    }
    __syncthreads();

    // ---- phase 5: combine: thread t -> (m, h) ----
    const int m = tid >> 3;
    const int h = tid & 7;
    const float* plp = pl + ((size_t)tok * Mq + m) * Pq;
    float p = 0.f;
#pragma unroll
    for (int pp = 0; pp < Pq; pp++) p = fmaf(plp[pp], sm.proj[pp][h], p);
    out[((size_t)tok * Mq + m) * Hq + h] = (sm.cont[m][h] + p + sm.kb[h]) * 0.125f;
}

// ---------------------------------------------------------------------------
// Launch
// Inputs: 0 pairwise_locations, 1 mask (unused), 2 query_features,
// 3 key_features, 4 nbhd_idx, 5 Wq, 6 Wk, 7 Wl, 8 u, 9 v
// ---------------------------------------------------------------------------
extern "C" void kernel_launch(void* const* d_in, const int* in_sizes, int n_in,
                              void* d_out, int out_size)
{
    const float* pl   = (const float*)d_in[0];
    const float* qf   = (const float*)d_in[2];
    const float* kf   = (const float*)d_in[3];
    const int*   nb   = (const int*)  d_in[4];
    const float* Wq_  = (const float*)d_in[5];
    const float* Wk_  = (const float*)d_in[6];
    const float* Wl   = (const float*)d_in[7];
    const float* u    = (const float*)d_in[8];
    const float* v    = (const float*)d_in[9];
    float*       out  = (float*)d_out;

    static int smem_set = 0;
    if (!smem_set) {
        cudaFuncSetAttribute(gemm_tc_kernel,
                             cudaFuncAttributeMaxDynamicSharedMemorySize, GEMM_SMEM);
        smem_set = 1;
    }

    prep_kernel<<<dim3(1280, 1, 2), 256>>>(qf, kf, Wq_, Wk_);
    gemm_tc_kernel<<<dim3(4, 32, 2), 256, GEMM_SMEM>>>();
    fuse_kernel<<<Bq * Nq, 256>>>(pl, nb, Wl, u, v, out);
}

// round 15
// speedup vs baseline: 1.1682x; 1.1682x over previous
#include <cuda_runtime.h>
#include <cuda_fp16.h>
#include <cstdint>

// Shapes (fixed by the problem)
#define Bq 2
#define Nq 2048
#define Mq 32
#define Hq 8
#define Dq 64
#define Eq 512
#define Fq 512
#define Pq 6

// ---------------------------------------------------------------------------
// Scratch (graph-capture rules forbid cudaMalloc)
// ---------------------------------------------------------------------------
__device__ __half g_P[2][Bq * Nq * Eq];   // fp16 projections: [0]=Q, [1]=K
__device__ __half g_x16[2][Bq * Nq * Fq]; // fp16 inputs: [0]=qf, [1]=kf
__device__ __half g_w16[2][Eq * Fq];      // fp16 transposed weights [n][k]

// ---------------------------------------------------------------------------
// helpers
// ---------------------------------------------------------------------------
__device__ __forceinline__ uint32_t smem_u32(const void* p) {
    uint32_t a;
    asm("{ .reg .u64 t; cvta.to.shared.u64 t, %1; cvt.u32.u64 %0, t; }" : "=r"(a) : "l"(p));
    return a;
}
__device__ __forceinline__ void cpasync16(uint32_t s, const void* g) {
    asm volatile("cp.async.cg.shared.global [%0], [%1], 16;" :: "r"(s), "l"(g));
}
__device__ __forceinline__ void ldsm_x4(uint32_t& r0, uint32_t& r1, uint32_t& r2, uint32_t& r3,
                                        uint32_t addr) {
    asm volatile("ldmatrix.sync.aligned.m8n8.x4.shared.b16 {%0,%1,%2,%3}, [%4];"
                 : "=r"(r0), "=r"(r1), "=r"(r2), "=r"(r3) : "r"(addr));
}
__device__ __forceinline__ void mma_f16(float* c, const uint32_t* a, uint32_t b0, uint32_t b1) {
    asm volatile(
        "mma.sync.aligned.m16n8k16.row.col.f32.f16.f16.f32 "
        "{%0,%1,%2,%3}, {%4,%5,%6,%7}, {%8,%9}, {%0,%1,%2,%3};"
        : "+f"(c[0]), "+f"(c[1]), "+f"(c[2]), "+f"(c[3])
        : "r"(a[0]), "r"(a[1]), "r"(a[2]), "r"(a[3]), "r"(b0), "r"(b1));
}
__device__ __forceinline__ void h8_to_f(const uint4& kv, float* f) {
    const __half2* hp = reinterpret_cast<const __half2*>(&kv);
#pragma unroll
    for (int i = 0; i < 4; i++) {
        float2 t = __half22float2(hp[i]);
        f[2 * i] = t.x;
        f[2 * i + 1] = t.y;
    }
}
__device__ __forceinline__ float red16(float s) {
    s += __shfl_xor_sync(0xffffffffu, s, 1);
    s += __shfl_xor_sync(0xffffffffu, s, 2);
    s += __shfl_xor_sync(0xffffffffu, s, 4);
    s += __shfl_xor_sync(0xffffffffu, s, 8);
    return s;
}
__device__ __forceinline__ float red8(float s) {
    s += __shfl_xor_sync(0xffffffffu, s, 1);
    s += __shfl_xor_sync(0xffffffffu, s, 2);
    s += __shfl_xor_sync(0xffffffffu, s, 4);
    return s;
}

// ---------------------------------------------------------------------------
// prep v2: blocks 0..1023 convert X fp32->fp16 — each thread reads 2
// CONSECUTIVE float4 (32B contiguous) and writes ONE uint4 (16B STG.128,
// half the store-issue cost of the old 2x STG.64).
// blocks 1024..1279 transpose+convert W. z=0 -> (qf,Wq); z=1 -> (kf,Wk).
// ---------------------------------------------------------------------------
__global__ __launch_bounds__(256) void prep_kernel(
    const float* __restrict__ qf, const float* __restrict__ kf,
    const float* __restrict__ Wq_, const float* __restrict__ Wk_)
{
    __shared__ float tile[32][33];
    const int z = blockIdx.z;
    const int tid = threadIdx.x;

    if (blockIdx.x < 1024) {
        const float* in = z ? kf : qf;
        __half* o = g_x16[z];
        const int f = blockIdx.x * 256 + tid;           // 0..262143 (uint4 out idx)
        float4 x0 = ((const float4*)in)[2 * f];
        float4 x1 = ((const float4*)in)[2 * f + 1];
        __half2 h0 = __floats2half2_rn(x0.x, x0.y);
        __half2 h1 = __floats2half2_rn(x0.z, x0.w);
        __half2 h2 = __floats2half2_rn(x1.x, x1.y);
        __half2 h3 = __floats2half2_rn(x1.z, x1.w);
        uint4 pk;
        pk.x = *(uint32_t*)&h0; pk.y = *(uint32_t*)&h1;
        pk.z = *(uint32_t*)&h2; pk.w = *(uint32_t*)&h3;
        ((uint4*)o)[f] = pk;
    } else {
        const int bx = blockIdx.x - 1024;               // 0..255
        const float* in = z ? Wk_ : Wq_;
        __half* o = g_w16[z];
        const int tx = tid & 31, ty = tid >> 5;         // 32 x 8
        const int n0 = (bx & 15) * 32, k0 = (bx >> 4) * 32;
#pragma unroll
        for (int j = 0; j < 4; j++)
            tile[ty + j * 8][tx] = in[(size_t)(k0 + ty + j * 8) * Eq + n0 + tx];
        __syncthreads();
#pragma unroll
        for (int j = 0; j < 4; j++)
            o[(size_t)(n0 + ty + j * 8) * Fq + k0 + tx] = __float2half_rn(tile[tx][ty + j * 8]);
    }
}

// ---------------------------------------------------------------------------
// GEMM (R9 exact): single-pass fp16 mma.sync, P[z] = X16 @ W16, fp16 out.
// CTA tile 128x128, 8 warps (2x4), warp tile 64x32, K-chunk 32,
// double-buffered cp.async. grid (4, 32, 2), 256 thr.
// ---------------------------------------------------------------------------
#define KC 32
#define LDE 40
#define TILE_B (128 * LDE * 2)
#define BUF_B (2 * TILE_B)
#define GEMM_SMEM (2 * BUF_B)        // 40960

__global__ __launch_bounds__(256, 2) void gemm_tc_kernel()
{
    extern __shared__ char smem[];
    const uint32_t sbase = smem_u32(smem);
    const int tid = threadIdx.x;
    const int wid = tid >> 5;
    const int lane = tid & 31;
    const int z = blockIdx.z;
    const int rowBase = blockIdx.y * 128;
    const int colBase = blockIdx.x * 128;

    const __half* X = g_x16[z];
    const __half* W = g_w16[z];
    __half* C = g_P[z];

    const int wm = (wid >> 2) * 64;
    const int wn = (wid & 3) * 32;

    const int r0a = tid >> 2, s0 = (tid & 3) * 8;
    const int r1a = (tid + 256) >> 2;

    float acc[4][4][4];
#pragma unroll
    for (int mt = 0; mt < 4; mt++)
#pragma unroll
        for (int nt = 0; nt < 4; nt++)
#pragma unroll
            for (int i = 0; i < 4; i++) acc[mt][nt][i] = 0.f;

    auto stage = [&](int buf, int kt) {
        const uint32_t sb = sbase + buf * BUF_B;
#pragma unroll
        for (int t = 0; t < 2; t++) {
            const int row = t ? r1a : r0a;
            const uint32_t so = (uint32_t)(row * LDE + s0) * 2;
            cpasync16(sb + so,          X + (size_t)(rowBase + row) * Fq + kt + s0);
            cpasync16(sb + TILE_B + so, W + (size_t)(colBase + row) * Fq + kt + s0);
        }
        asm volatile("cp.async.commit_group;");
    };

    const int lj = lane >> 3, lr = lane & 7;
    const int arow = (lj & 1) * 8 + lr;
    const int acol = (lj >> 1) * 8;
    const int brow = (lj >> 1) * 8 + lr;
    const int bcol = (lj & 1) * 8;

    stage(0, 0);

    const int NCHUNK = Fq / KC;               // 16
    for (int c = 0; c < NCHUNK; c++) {
        if (c + 1 < NCHUNK) stage((c + 1) & 1, (c + 1) * KC);
        if (c + 1 < NCHUNK) asm volatile("cp.async.wait_group 1;");
        else                asm volatile("cp.async.wait_group 0;");
        __syncthreads();

        const uint32_t sb = sbase + (c & 1) * BUF_B;
#pragma unroll
        for (int ks = 0; ks < 2; ks++) {
            const int kof = ks * 16;
            uint32_t a[4][4], bfr[2][4];
#pragma unroll
            for (int mt = 0; mt < 4; mt++)
                ldsm_x4(a[mt][0], a[mt][1], a[mt][2], a[mt][3],
                        sb + (uint32_t)((wm + mt * 16 + arow) * LDE + kof + acol) * 2);
#pragma unroll
            for (int np = 0; np < 2; np++)
                ldsm_x4(bfr[np][0], bfr[np][1], bfr[np][2], bfr[np][3],
                        sb + TILE_B + (uint32_t)((wn + np * 16 + brow) * LDE + kof + bcol) * 2);
#pragma unroll
            for (int mt = 0; mt < 4; mt++)
#pragma unroll
                for (int nt = 0; nt < 4; nt++)
                    mma_f16(acc[mt][nt], a[mt],
                            bfr[nt >> 1][(nt & 1) * 2], bfr[nt >> 1][(nt & 1) * 2 + 1]);
        }
        __syncthreads();
    }

    const int g = lane >> 2, tg = lane & 3;
#pragma unroll
    for (int mt = 0; mt < 4; mt++)
#pragma unroll
        for (int nt = 0; nt < 4; nt++) {
            const int row = rowBase + wm + mt * 16 + g;
            const int col = colBase + wn + nt * 8 + 2 * tg;
            *(__half2*)(C + (size_t)row * Eq + col) =
                __floats2half2_rn(acc[mt][nt][0], acc[mt][nt][1]);
            *(__half2*)(C + (size_t)(row + 8) * Eq + col) =
                __floats2half2_rn(acc[mt][nt][2], acc[mt][nt][3]);
        }
}

// ---------------------------------------------------------------------------
// Fused epilogue v4 (R9 exact — best known): one CTA (256 thr) per TWO tokens.
// Warps 0-3 -> token 0, warps 4-7 -> token 1. Content 8 rows/warp in 4-row
// batches (register gather). Head maps: content e=c*256+l*8+j -> h=4c+(l>>3);
// proj e=c*128+l*4+j -> h=2c+(l>>4).
// ---------------------------------------------------------------------------
__global__ __launch_bounds__(256) void fuse_kernel(
    const float* __restrict__ pl,     // (B,N,M,P)
    const int*   __restrict__ nbhd,   // (B,N,M)
    const float* __restrict__ Wl,     // (P,E)
    const float* __restrict__ u,      // 512 contiguous
    const float* __restrict__ v,      // 512 contiguous
    float*       __restrict__ out)    // (B,N,M,H)
{
    __shared__ float proj[2][Pq][Hq];
    __shared__ float kb[2][Hq];
    __shared__ float cont[2][Mq][Hq];

    const int tid = threadIdx.x;
    const int w = tid >> 5;
    const int l = tid & 31;
    const int t = w >> 2;             // token within CTA
    const int g = w & 3;              // warp within group
    const int tok = blockIdx.x * 2 + t;   // 0..4095
    const int b = tok >> 11;

    const __half* Qh = g_P[0] + (size_t)tok * Eq;
    const __half* Khb = g_P[1] + (size_t)b * Nq * Eq;
    const int* nbp = nbhd + (size_t)tok * Mq;

    // ---- content Q slice: 2 contiguous uint4 of halves ----
    float q16[16];
#pragma unroll
    for (int c = 0; c < 2; c++) {
        uint4 qv = *(const uint4*)(Qh + c * 256 + l * 8);
        h8_to_f(qv, q16 + c * 8);
    }

    // ---- content: 8 rows per warp (m = g + 4*jj), batched 4 rows ----
#pragma unroll
    for (int jb = 0; jb < 2; jb++) {
        uint4 kv[4][2];
        int mr[4];
#pragma unroll
        for (int i = 0; i < 4; i++) {
            mr[i] = g + 4 * (jb * 4 + i);
            const __half* Kp = Khb + (size_t)nbp[mr[i]] * Eq;
            kv[i][0] = *(const uint4*)(Kp + l * 8);
            kv[i][1] = *(const uint4*)(Kp + 256 + l * 8);
        }
#pragma unroll
        for (int i = 0; i < 4; i++) {
#pragma unroll
            for (int c = 0; c < 2; c++) {
                float kf[8];
                h8_to_f(kv[i][c], kf);
                float s = 0.f;
#pragma unroll
                for (int j = 0; j < 8; j++) s = fmaf(kf[j], q16[c * 8 + j], s);
                s = red8(s);
                if ((l & 7) == 0) cont[t][mr[i]][c * 4 + (l >> 3)] = s;
            }
        }
    }

    // ---- proj (warps g=0..2: rows 2g, 2g+1) / kb (warp g=3) ----
    if (g < 3) {
        const int hsub = l >> 4;
#pragma unroll
        for (int pi = 0; pi < 2; pi++) {
            const int pr = g * 2 + pi;
            const float* wlr = Wl + pr * Eq;
            float psum[4];
#pragma unroll
            for (int c = 0; c < 4; c++) {
                uint2 qp = *(const uint2*)(Qh + c * 128 + l * 4);
                float2 q0 = __half22float2(*(const __half2*)&qp.x);
                float2 q1 = __half22float2(*(const __half2*)&qp.y);
                float4 wv = *(const float4*)(wlr + c * 128 + l * 4);
                float4 vf = *(const float4*)(v + c * 128 + l * 4);
                float s = 0.f;
                s = fmaf(wv.x, q0.x + vf.x, s);
                s = fmaf(wv.y, q0.y + vf.y, s);
                s = fmaf(wv.z, q1.x + vf.z, s);
                s = fmaf(wv.w, q1.y + vf.w, s);
                psum[c] = red16(s);
            }
            if ((l & 15) == 0) {
#pragma unroll
                for (int c = 0; c < 4; c++) proj[t][pr][2 * c + hsub] = psum[c];
            }
        }
    } else {
        const __half* Kg = g_P[1] + (size_t)tok * Eq;
#pragma unroll
        for (int c = 0; c < 2; c++) {
            uint4 kk = *(const uint4*)(Kg + c * 256 + l * 8);
            float kf[8];
            h8_to_f(kk, kf);
            float4 u0 = *(const float4*)(u + c * 256 + l * 8);
            float4 u1 = *(const float4*)(u + c * 256 + l * 8 + 4);
            float s = 0.f;
            s = fmaf(kf[0], u0.x, s); s = fmaf(kf[1], u0.y, s);
            s = fmaf(kf[2], u0.z, s); s = fmaf(kf[3], u0.w, s);
            s = fmaf(kf[4], u1.x, s); s = fmaf(kf[5], u1.y, s);
            s = fmaf(kf[6], u1.z, s); s = fmaf(kf[7], u1.w, s);
            s = red8(s);
            if ((l & 7) == 0) kb[t][c * 4 + (l >> 3)] = s;
        }
    }
    __syncthreads();

    // ---- combine: 128 threads per token, 2 outputs each ----
    const int tt = tid >> 7;
    const int rest = tid & 127;
    const int m = rest >> 2;
    const int h0 = (rest & 3) * 2;
    const int tko = blockIdx.x * 2 + tt;
    const float* plp = pl + ((size_t)tko * Mq + m) * Pq;
    float plr[Pq];
#pragma unroll
    for (int pp = 0; pp < Pq; pp++) plr[pp] = plp[pp];

    float p0 = 0.f, p1 = 0.f;
#pragma unroll
    for (int pp = 0; pp < Pq; pp++) {
        p0 = fmaf(plr[pp], proj[tt][pp][h0], p0);
        p1 = fmaf(plr[pp], proj[tt][pp][h0 + 1], p1);
    }
    float* op = out + ((size_t)tko * Mq + m) * Hq + h0;
    op[0] = (cont[tt][m][h0] + p0 + kb[tt][h0]) * 0.125f;
    op[1] = (cont[tt][m][h0 + 1] + p1 + kb[tt][h0 + 1]) * 0.125f;
}

// ---------------------------------------------------------------------------
// Launch
// Inputs: 0 pairwise_locations, 1 mask (unused), 2 query_features,
// 3 key_features, 4 nbhd_idx, 5 Wq, 6 Wk, 7 Wl, 8 u, 9 v
// ---------------------------------------------------------------------------
extern "C" void kernel_launch(void* const* d_in, const int* in_sizes, int n_in,
                              void* d_out, int out_size)
{
    const float* pl   = (const float*)d_in[0];
    const float* qf   = (const float*)d_in[2];
    const float* kf   = (const float*)d_in[3];
    const int*   nb   = (const int*)  d_in[4];
    const float* Wq_  = (const float*)d_in[5];
    const float* Wk_  = (const float*)d_in[6];
    const float* Wl   = (const float*)d_in[7];
    const float* u    = (const float*)d_in[8];
    const float* v    = (const float*)d_in[9];
    float*       out  = (float*)d_out;

    static int smem_set = 0;
    if (!smem_set) {
        cudaFuncSetAttribute(gemm_tc_kernel,
                             cudaFuncAttributeMaxDynamicSharedMemorySize, GEMM_SMEM);
        smem_set = 1;
    }

    prep_kernel<<<dim3(1280, 1, 2), 256>>>(qf, kf, Wq_, Wk_);
    gemm_tc_kernel<<<dim3(4, 32, 2), 256, GEMM_SMEM>>>();
    fuse_kernel<<<Bq * Nq / 2, 256>>>(pl, nb, Wl, u, v, out);
}